// round 1
// baseline (speedup 1.0000x reference)
#include <cuda_runtime.h>
#include <math.h>

#define MAXN 50000
#define MAXE 1600000
#define DDIM 128

struct __align__(8) Edge { int s; float c; };

// ---- device scratch (no allocation allowed) ----
__device__ int   g_indeg[MAXN];
__device__ int   g_outdeg[MAXN];
__device__ int   g_fill[MAXN];
__device__ int   g_rowptr[MAXN + 1];
__device__ float g_wet[8];
__device__ Edge  g_edges[MAXE];
__device__ float g_h0[(size_t)MAXN * DDIM];
__device__ float g_h1[(size_t)MAXN * DDIM];

// ---------------------------------------------------------------------------
// 1) zero counters
__global__ void zero_kernel(int N) {
    int i = blockIdx.x * blockDim.x + threadIdx.x;
    int stride = gridDim.x * blockDim.x;
    for (; i < N; i += stride) {
        g_indeg[i] = 0; g_outdeg[i] = 0; g_fill[i] = 0;
    }
}

// ---------------------------------------------------------------------------
// 2) per-etype gate: wet[t] = 1 + sigmoid( gelu(emb[t]@We1+be1) @ We2 + be2 )
__global__ void gate_kernel(const float* __restrict__ emb,
                            const float* __restrict__ We1, const float* __restrict__ be1,
                            const float* __restrict__ We2, const float* __restrict__ be2) {
    __shared__ float eh[8][32];
    int t = threadIdx.x;          // 256 threads
    int et = t >> 5, j = t & 31;
    float dot = be1[j];
    #pragma unroll 8
    for (int i = 0; i < 128; i++) dot += emb[et * 128 + i] * We1[i * 32 + j];
    // exact gelu
    float g = 0.5f * dot * (1.0f + erff(dot * 0.70710678118654752f));
    eh[et][j] = g;
    __syncthreads();
    if (j == 0) {
        float d2 = be2[0];
        #pragma unroll
        for (int jj = 0; jj < 32; jj++) d2 += eh[et][jj] * We2[jj];
        float sg = 1.0f / (1.0f + expf(-d2));
        g_wet[et] = 1.0f + sg;
    }
}

// ---------------------------------------------------------------------------
// 3) degree histograms
__global__ void hist_kernel(const int* __restrict__ src, const int* __restrict__ dst, int E) {
    int i = blockIdx.x * blockDim.x + threadIdx.x;
    int stride = gridDim.x * blockDim.x;
    for (; i < E; i += stride) {
        atomicAdd(&g_outdeg[src[i]], 1);
        atomicAdd(&g_indeg[dst[i]], 1);
    }
}

// ---------------------------------------------------------------------------
// 4) exclusive scan of in-degrees -> rowptr (single block, 1024 threads)
__global__ void scan_kernel(int N) {
    __shared__ int ps[1024];
    int t = threadIdx.x;
    int C = (N + 1023) >> 10;
    int start = t * C;
    int local = 0;
    for (int i = 0; i < C; i++) {
        int idx = start + i;
        if (idx < N) local += g_indeg[idx];
    }
    ps[t] = local;
    __syncthreads();
    // Hillis-Steele inclusive scan
    for (int off = 1; off < 1024; off <<= 1) {
        int v = (t >= off) ? ps[t - off] : 0;
        __syncthreads();
        ps[t] += v;
        __syncthreads();
    }
    int run = ps[t] - local;   // exclusive prefix for this thread's chunk
    for (int i = 0; i < C; i++) {
        int idx = start + i;
        if (idx < N) {
            g_rowptr[idx] = run;
            run += g_indeg[idx];
        }
    }
    if (t == 1023) g_rowptr[N] = ps[1023];
}

// ---------------------------------------------------------------------------
// 5) scatter edges into CSR, folding all per-edge scalars into c
__global__ void scatter_kernel(const int* __restrict__ src, const int* __restrict__ dst,
                               const int* __restrict__ ef, int E) {
    int i = blockIdx.x * blockDim.x + threadIdx.x;
    int stride = gridDim.x * blockDim.x;
    for (; i < E; i += stride) {
        int s = src[i], d = dst[i];
        float sn = rsqrtf((float)max(g_outdeg[s], 1));
        float dn = rsqrtf((float)max(g_indeg[d], 1));
        float c = g_wet[ef[i]] * sn * dn;
        int pos = g_rowptr[d] + atomicAdd(&g_fill[d], 1);
        Edge e; e.s = s; e.c = c;
        g_edges[pos] = e;
    }
}

// ---------------------------------------------------------------------------
// 6) one propagation hop: warp per dst row, float4 per lane
__global__ void __launch_bounds__(256) hop_kernel(const float* __restrict__ feat, int hop, int N) {
    int gw = (blockIdx.x * blockDim.x + threadIdx.x) >> 5;
    if (gw >= N) return;
    int lane = threadIdx.x & 31;

    const float4* h_in = (hop == 0) ? (const float4*)feat
                        : ((hop & 1) ? (const float4*)g_h0 : (const float4*)g_h1);
    float4* h_out = (hop & 1) ? (float4*)g_h1 : (float4*)g_h0;

    int beg = g_rowptr[gw];
    int end = g_rowptr[gw + 1];

    float4 acc = make_float4(0.f, 0.f, 0.f, 0.f);
    for (int base = beg; base < end; base += 32) {
        int n = min(32, end - base);
        int   es = 0;
        float ec = 0.f;
        if (base + lane < end) {
            Edge e = g_edges[base + lane];
            es = e.s; ec = e.c;
        }
        for (int j = 0; j < n; ++j) {
            int   s = __shfl_sync(0xffffffffu, es, j);
            float c = __shfl_sync(0xffffffffu, ec, j);
            float4 v = __ldg(&h_in[s * 32 + lane]);
            acc.x = fmaf(c, v.x, acc.x);
            acc.y = fmaf(c, v.y, acc.y);
            acc.z = fmaf(c, v.z, acc.z);
            acc.w = fmaf(c, v.w, acc.w);
        }
    }
    float4 f0 = ((const float4*)feat)[gw * 32 + lane];
    float4 o;
    o.x = 0.9f * acc.x + 0.1f * f0.x;
    o.y = 0.9f * acc.y + 0.1f * f0.y;
    o.z = 0.9f * acc.z + 0.1f * f0.z;
    o.w = 0.9f * acc.w + 0.1f * f0.w;
    h_out[gw * 32 + lane] = o;
}

// ---------------------------------------------------------------------------
// 7) GEMM (M x 128) @ (128 x 128), optional exact-GELU epilogue
//    dynamic smem: W (64KB) + A tile 64x128 (32KB) = 96KB
template <bool GELU>
__global__ void __launch_bounds__(256) gemm128_kernel(const float* __restrict__ A,
                                                      const float* __restrict__ W,
                                                      const float* __restrict__ bias,
                                                      float* __restrict__ Out, int M) {
    extern __shared__ float smem[];
    float* Ws = smem;            // 128*128
    float* As = smem + 16384;    // 64*128

    int t = threadIdx.x;         // 256
    const float4* Wv = (const float4*)W;
    float4* Wsv = (float4*)Ws;
    #pragma unroll
    for (int i = t; i < 4096; i += 256) Wsv[i] = Wv[i];

    int row0 = blockIdx.x * 64;
    const float4* Av = (const float4*)A;
    float4* Asv = (float4*)As;
    for (int i = t; i < 2048; i += 256) {
        int r = i >> 5;
        int gr = row0 + r;
        Asv[i] = (gr < M) ? Av[gr * 32 + (i & 31)] : make_float4(0.f, 0.f, 0.f, 0.f);
    }
    __syncthreads();

    int tx = t & 31, ty = t >> 5;  // ty in [0,8)
    int r0 = ty * 8, c0 = tx * 4;

    float acc[8][4];
    #pragma unroll
    for (int i = 0; i < 8; i++)
        #pragma unroll
        for (int j = 0; j < 4; j++) acc[i][j] = 0.f;

    #pragma unroll 8
    for (int k = 0; k < 128; k++) {
        float4 w = *(const float4*)&Ws[k * 128 + c0];
        float a[8];
        #pragma unroll
        for (int i = 0; i < 8; i++) a[i] = As[(r0 + i) * 128 + k];
        #pragma unroll
        for (int i = 0; i < 8; i++) {
            acc[i][0] = fmaf(a[i], w.x, acc[i][0]);
            acc[i][1] = fmaf(a[i], w.y, acc[i][1]);
            acc[i][2] = fmaf(a[i], w.z, acc[i][2]);
            acc[i][3] = fmaf(a[i], w.w, acc[i][3]);
        }
    }

    float4 b = *(const float4*)&bias[c0];
    #pragma unroll
    for (int i = 0; i < 8; i++) {
        int row = row0 + r0 + i;
        if (row < M) {
            float4 o;
            o.x = acc[i][0] + b.x;
            o.y = acc[i][1] + b.y;
            o.z = acc[i][2] + b.z;
            o.w = acc[i][3] + b.w;
            if (GELU) {
                o.x = 0.5f * o.x * (1.0f + erff(o.x * 0.70710678118654752f));
                o.y = 0.5f * o.y * (1.0f + erff(o.y * 0.70710678118654752f));
                o.z = 0.5f * o.z * (1.0f + erff(o.z * 0.70710678118654752f));
                o.w = 0.5f * o.w * (1.0f + erff(o.w * 0.70710678118654752f));
            }
            *(float4*)&Out[row * 128 + c0] = o;
        }
    }
}

// ---------------------------------------------------------------------------
extern "C" void kernel_launch(void* const* d_in, const int* in_sizes, int n_in,
                              void* d_out, int out_size) {
    const float* feat = (const float*)d_in[0];
    const int*   ef   = (const int*)d_in[1];
    const int*   src  = (const int*)d_in[2];
    const int*   dst  = (const int*)d_in[3];
    const float* emb  = (const float*)d_in[4];
    const float* We1  = (const float*)d_in[5];
    const float* be1  = (const float*)d_in[6];
    const float* We2  = (const float*)d_in[7];
    const float* be2  = (const float*)d_in[8];
    const float* W1   = (const float*)d_in[9];
    const float* b1   = (const float*)d_in[10];
    const float* W2   = (const float*)d_in[11];
    const float* b2   = (const float*)d_in[12];
    float* out = (float*)d_out;

    int N = in_sizes[0] / DDIM;   // 50000
    int E = in_sizes[1];          // 1600000

    // scratch base pointers for GEMM stage
    void *p0 = nullptr, *p1 = nullptr;
    cudaGetSymbolAddress(&p0, g_h0);
    cudaGetSymbolAddress(&p1, g_h1);
    float* h0 = (float*)p0;
    float* h1 = (float*)p1;

    static bool attr_set = false;
    // idempotent attribute set (not a stream op; legal during capture)
    cudaFuncSetAttribute(gemm128_kernel<true>,  cudaFuncAttributeMaxDynamicSharedMemorySize, 98304);
    cudaFuncSetAttribute(gemm128_kernel<false>, cudaFuncAttributeMaxDynamicSharedMemorySize, 98304);
    (void)attr_set;

    // --- build phase ---
    zero_kernel<<<(N + 255) / 256, 256>>>(N);
    gate_kernel<<<1, 256>>>(emb, We1, be1, We2, be2);
    hist_kernel<<<2048, 256>>>(src, dst, E);
    scan_kernel<<<1, 1024>>>(N);
    scatter_kernel<<<2048, 256>>>(src, dst, ef, E);

    // --- K=10 propagation hops ---
    int hop_blocks = (N * 32 + 255) / 256;
    for (int k = 0; k < 10; k++)
        hop_kernel<<<hop_blocks, 256>>>(feat, k, N);
    // final h lives in g_h1 (hop 9 writes h1)

    // --- output MLP ---
    int gblocks = (N + 63) / 64;
    gemm128_kernel<true ><<<gblocks, 256, 98304>>>(h1, W1, b1, h0, N);
    gemm128_kernel<false><<<gblocks, 256, 98304>>>(h0, W2, b2, out, N);
}

// round 2
// speedup vs baseline: 1.3035x; 1.3035x over previous
#include <cuda_runtime.h>
#include <cuda_fp16.h>
#include <math.h>

#define MAXN 50000
#define MAXE 1600000
#define DDIM 128
#define SCB 256   // scan chunk/block size
#define MAXSB 256 // max scan blocks (ceil(50000/256)=196)

struct __align__(8) Edge { int s; float c; };

// ---- device scratch (no allocation allowed) ----
__device__ int    g_indeg[MAXN];
__device__ int    g_outdeg[MAXN];
__device__ int    g_fill[MAXN];
__device__ int    g_rowptr[MAXN + 1];
__device__ int    g_blocksum[MAXSB];
__device__ int    g_blockoff[MAXSB];
__device__ float  g_wet[8];
__device__ Edge   g_edges[MAXE];
__device__ __half g_ha[(size_t)MAXN * DDIM];   // half ping
__device__ __half g_hb[(size_t)MAXN * DDIM];   // half pong
__device__ float  g_h0[(size_t)MAXN * DDIM];   // fp32 final h / gemm scratch
__device__ float  g_h1[(size_t)MAXN * DDIM];   // fp32 gemm intermediate

// ---------------------------------------------------------------------------
__global__ void zero_kernel(int N) {
    int i = blockIdx.x * blockDim.x + threadIdx.x;
    int stride = gridDim.x * blockDim.x;
    for (; i < N; i += stride) {
        g_indeg[i] = 0; g_outdeg[i] = 0; g_fill[i] = 0;
    }
}

// ---------------------------------------------------------------------------
// per-etype gate: wet[t] = 1 + sigmoid( gelu(emb[t]@We1+be1) @ We2 + be2 )
__global__ void gate_kernel(const float* __restrict__ emb,
                            const float* __restrict__ We1, const float* __restrict__ be1,
                            const float* __restrict__ We2, const float* __restrict__ be2) {
    __shared__ float eh[8][32];
    int t = threadIdx.x;          // 256 threads
    int et = t >> 5, j = t & 31;
    float dot = be1[j];
    #pragma unroll 8
    for (int i = 0; i < 128; i++) dot += emb[et * 128 + i] * We1[i * 32 + j];
    float g = 0.5f * dot * (1.0f + erff(dot * 0.70710678118654752f));
    eh[et][j] = g;
    __syncthreads();
    if (j == 0) {
        float d2 = be2[0];
        #pragma unroll
        for (int jj = 0; jj < 32; jj++) d2 += eh[et][jj] * We2[jj];
        float sg = 1.0f / (1.0f + expf(-d2));
        g_wet[et] = 1.0f + sg;
    }
}

// ---------------------------------------------------------------------------
__global__ void hist_kernel(const int* __restrict__ src, const int* __restrict__ dst, int E) {
    int i = blockIdx.x * blockDim.x + threadIdx.x;
    int stride = gridDim.x * blockDim.x;
    for (; i < E; i += stride) {
        atomicAdd(&g_outdeg[src[i]], 1);
        atomicAdd(&g_indeg[dst[i]], 1);
    }
}

// ---------------------------------------------------------------------------
// 3-phase exclusive scan of in-degrees -> rowptr
__global__ void scan_phase1(int N) {
    __shared__ int s[SCB];
    int b = blockIdx.x, t = threadIdx.x;
    int idx = b * SCB + t;
    int v = (idx < N) ? g_indeg[idx] : 0;
    s[t] = v; __syncthreads();
    #pragma unroll
    for (int off = SCB / 2; off > 0; off >>= 1) {
        if (t < off) s[t] += s[t + off];
        __syncthreads();
    }
    if (t == 0) g_blocksum[b] = s[0];
}

__global__ void scan_phase2(int NB, int N) {
    __shared__ int s[SCB];
    int t = threadIdx.x;
    int v = (t < NB) ? g_blocksum[t] : 0;
    s[t] = v; __syncthreads();
    #pragma unroll
    for (int off = 1; off < SCB; off <<= 1) {
        int x = (t >= off) ? s[t - off] : 0;
        __syncthreads();
        s[t] += x;
        __syncthreads();
    }
    g_blockoff[t] = s[t] - v;           // exclusive block offset
    if (t == NB - 1) g_rowptr[N] = s[t]; // total edge count
}

__global__ void scan_phase3(int N) {
    __shared__ int s[SCB];
    int b = blockIdx.x, t = threadIdx.x;
    int idx = b * SCB + t;
    int v = (idx < N) ? g_indeg[idx] : 0;
    s[t] = v; __syncthreads();
    #pragma unroll
    for (int off = 1; off < SCB; off <<= 1) {
        int x = (t >= off) ? s[t - off] : 0;
        __syncthreads();
        s[t] += x;
        __syncthreads();
    }
    if (idx < N) g_rowptr[idx] = g_blockoff[b] + s[t] - v;
}

// ---------------------------------------------------------------------------
__global__ void scatter_kernel(const int* __restrict__ src, const int* __restrict__ dst,
                               const int* __restrict__ ef, int E) {
    int i = blockIdx.x * blockDim.x + threadIdx.x;
    int stride = gridDim.x * blockDim.x;
    for (; i < E; i += stride) {
        int s = src[i], d = dst[i];
        float sn = rsqrtf((float)max(g_outdeg[s], 1));
        float dn = rsqrtf((float)max(g_indeg[d], 1));
        float c = g_wet[ef[i]] * sn * dn;
        int pos = g_rowptr[d] + atomicAdd(&g_fill[d], 1);
        Edge e; e.s = s; e.c = c;
        g_edges[pos] = e;
    }
}

// ---------------------------------------------------------------------------
// convert fp32 feat -> half buffer (hop 0 input)
__global__ void f2h_kernel(const float* __restrict__ in, __half* __restrict__ out, int n4) {
    int i = blockIdx.x * blockDim.x + threadIdx.x;
    if (i >= n4) return;
    float4 v = ((const float4*)in)[i];
    __half2 a = __floats2half2_rn(v.x, v.y);
    __half2 b = __floats2half2_rn(v.z, v.w);
    uint2 o; o.x = *(unsigned*)&a; o.y = *(unsigned*)&b;
    ((uint2*)out)[i] = o;
}

// ---------------------------------------------------------------------------
// one hop: warp per dst row, lane = 4 consecutive features (8B half load)
// LAST: write fp32 for the GEMM stage; else write half ping-pong
template <bool LAST>
__global__ void __launch_bounds__(256) hop_kernel(const __half* __restrict__ hin,
                                                  const float* __restrict__ feat,
                                                  __half* __restrict__ houth,
                                                  float* __restrict__ houtf, int N) {
    int gw = (blockIdx.x * blockDim.x + threadIdx.x) >> 5;
    if (gw >= N) return;
    int lane = threadIdx.x & 31;

    int beg = g_rowptr[gw];
    int end = g_rowptr[gw + 1];

    float4 acc = make_float4(0.f, 0.f, 0.f, 0.f);
    for (int base = beg; base < end; base += 32) {
        int n = min(32, end - base);
        int   es = 0;
        float ec = 0.f;
        if (base + lane < end) {
            Edge e = g_edges[base + lane];
            es = e.s; ec = e.c;
        }
        for (int j = 0; j < n; ++j) {
            int   s = __shfl_sync(0xffffffffu, es, j);
            float c = __shfl_sync(0xffffffffu, ec, j);
            uint2 v = __ldg((const uint2*)(hin + (size_t)s * DDIM) + lane);
            __half2 p0 = *(__half2*)&v.x;
            __half2 p1 = *(__half2*)&v.y;
            float2 f0 = __half22float2(p0);
            float2 f1 = __half22float2(p1);
            acc.x = fmaf(c, f0.x, acc.x);
            acc.y = fmaf(c, f0.y, acc.y);
            acc.z = fmaf(c, f1.x, acc.z);
            acc.w = fmaf(c, f1.y, acc.w);
        }
    }
    float4 f0 = ((const float4*)feat)[gw * 32 + lane];
    float ox = 0.9f * acc.x + 0.1f * f0.x;
    float oy = 0.9f * acc.y + 0.1f * f0.y;
    float oz = 0.9f * acc.z + 0.1f * f0.z;
    float ow = 0.9f * acc.w + 0.1f * f0.w;
    if (LAST) {
        float4 o = make_float4(ox, oy, oz, ow);
        ((float4*)houtf)[gw * 32 + lane] = o;
    } else {
        __half2 a = __floats2half2_rn(ox, oy);
        __half2 b = __floats2half2_rn(oz, ow);
        uint2 o; o.x = *(unsigned*)&a; o.y = *(unsigned*)&b;
        ((uint2*)houth)[gw * 32 + lane] = o;
    }
}

// ---------------------------------------------------------------------------
// GEMM (M x 128) @ (128 x 128), optional exact-GELU epilogue
template <bool GELU>
__global__ void __launch_bounds__(256) gemm128_kernel(const float* __restrict__ A,
                                                      const float* __restrict__ W,
                                                      const float* __restrict__ bias,
                                                      float* __restrict__ Out, int M) {
    extern __shared__ float smem[];
    float* Ws = smem;            // 128*128
    float* As = smem + 16384;    // 64*128

    int t = threadIdx.x;         // 256
    const float4* Wv = (const float4*)W;
    float4* Wsv = (float4*)Ws;
    #pragma unroll
    for (int i = t; i < 4096; i += 256) Wsv[i] = Wv[i];

    int row0 = blockIdx.x * 64;
    const float4* Av = (const float4*)A;
    float4* Asv = (float4*)As;
    for (int i = t; i < 2048; i += 256) {
        int r = i >> 5;
        int gr = row0 + r;
        Asv[i] = (gr < M) ? Av[gr * 32 + (i & 31)] : make_float4(0.f, 0.f, 0.f, 0.f);
    }
    __syncthreads();

    int tx = t & 31, ty = t >> 5;  // ty in [0,8)
    int r0 = ty * 8, c0 = tx * 4;

    float acc[8][4];
    #pragma unroll
    for (int i = 0; i < 8; i++)
        #pragma unroll
        for (int j = 0; j < 4; j++) acc[i][j] = 0.f;

    #pragma unroll 8
    for (int k = 0; k < 128; k++) {
        float4 w = *(const float4*)&Ws[k * 128 + c0];
        float a[8];
        #pragma unroll
        for (int i = 0; i < 8; i++) a[i] = As[(r0 + i) * 128 + k];
        #pragma unroll
        for (int i = 0; i < 8; i++) {
            acc[i][0] = fmaf(a[i], w.x, acc[i][0]);
            acc[i][1] = fmaf(a[i], w.y, acc[i][1]);
            acc[i][2] = fmaf(a[i], w.z, acc[i][2]);
            acc[i][3] = fmaf(a[i], w.w, acc[i][3]);
        }
    }

    float4 b = *(const float4*)&bias[c0];
    #pragma unroll
    for (int i = 0; i < 8; i++) {
        int row = row0 + r0 + i;
        if (row < M) {
            float4 o;
            o.x = acc[i][0] + b.x;
            o.y = acc[i][1] + b.y;
            o.z = acc[i][2] + b.z;
            o.w = acc[i][3] + b.w;
            if (GELU) {
                o.x = 0.5f * o.x * (1.0f + erff(o.x * 0.70710678118654752f));
                o.y = 0.5f * o.y * (1.0f + erff(o.y * 0.70710678118654752f));
                o.z = 0.5f * o.z * (1.0f + erff(o.z * 0.70710678118654752f));
                o.w = 0.5f * o.w * (1.0f + erff(o.w * 0.70710678118654752f));
            }
            *(float4*)&Out[row * 128 + c0] = o;
        }
    }
}

// ---------------------------------------------------------------------------
extern "C" void kernel_launch(void* const* d_in, const int* in_sizes, int n_in,
                              void* d_out, int out_size) {
    const float* feat = (const float*)d_in[0];
    const int*   ef   = (const int*)d_in[1];
    const int*   src  = (const int*)d_in[2];
    const int*   dst  = (const int*)d_in[3];
    const float* emb  = (const float*)d_in[4];
    const float* We1  = (const float*)d_in[5];
    const float* be1  = (const float*)d_in[6];
    const float* We2  = (const float*)d_in[7];
    const float* be2  = (const float*)d_in[8];
    const float* W1   = (const float*)d_in[9];
    const float* b1   = (const float*)d_in[10];
    const float* W2   = (const float*)d_in[11];
    const float* b2   = (const float*)d_in[12];
    float* out = (float*)d_out;

    int N = in_sizes[0] / DDIM;   // 50000
    int E = in_sizes[1];          // 1600000

    void *p0 = nullptr, *p1 = nullptr, *pa = nullptr, *pb = nullptr;
    cudaGetSymbolAddress(&p0, g_h0);
    cudaGetSymbolAddress(&p1, g_h1);
    cudaGetSymbolAddress(&pa, g_ha);
    cudaGetSymbolAddress(&pb, g_hb);
    float*  h0 = (float*)p0;
    float*  h1 = (float*)p1;
    __half* ha = (__half*)pa;
    __half* hb = (__half*)pb;

    cudaFuncSetAttribute(gemm128_kernel<true>,  cudaFuncAttributeMaxDynamicSharedMemorySize, 98304);
    cudaFuncSetAttribute(gemm128_kernel<false>, cudaFuncAttributeMaxDynamicSharedMemorySize, 98304);

    // --- build phase ---
    zero_kernel<<<(N + 255) / 256, 256>>>(N);
    gate_kernel<<<1, 256>>>(emb, We1, be1, We2, be2);
    hist_kernel<<<2048, 256>>>(src, dst, E);
    int NB = (N + SCB - 1) / SCB;  // 196
    scan_phase1<<<NB, SCB>>>(N);
    scan_phase2<<<1, SCB>>>(NB, N);
    scan_phase3<<<NB, SCB>>>(N);
    scatter_kernel<<<2048, 256>>>(src, dst, ef, E);

    // feat -> half
    int n4 = N * DDIM / 4;
    f2h_kernel<<<(n4 + 255) / 256, 256>>>(feat, ha, n4);

    // --- K=10 propagation hops (half ping-pong; last hop writes fp32 h0) ---
    int hop_blocks = (N * 32 + 255) / 256;
    for (int k = 0; k < 9; k++) {
        const __half* hin = (k & 1) ? hb : ha;
        __half*       hout = (k & 1) ? ha : hb;
        hop_kernel<false><<<hop_blocks, 256>>>(hin, feat, hout, nullptr, N);
    }
    // hop 9: input hb (k=9 odd), output fp32 h0
    hop_kernel<true><<<hop_blocks, 256>>>(hb, feat, nullptr, h0, N);

    // --- output MLP ---
    int gblocks = (N + 63) / 64;
    gemm128_kernel<true ><<<gblocks, 256, 98304>>>(h0, W1, b1, h1, N);
    gemm128_kernel<false><<<gblocks, 256, 98304>>>(h1, W2, b2, out, N);
}

// round 3
// speedup vs baseline: 1.5198x; 1.1659x over previous
#include <cuda_runtime.h>
#include <cuda_fp16.h>
#include <mma.h>
#include <math.h>

using namespace nvcuda;

#define MAXN 50000
#define PADN 50176   // 392*128, covers GEMM row tiles
#define MAXE 1600000
#define DDIM 128
#define SCB 256
#define MAXSB 256

struct __align__(8) Edge { int s; float c; };

// ---- device scratch (no allocation allowed) ----
__device__ int    g_indeg[MAXN];
__device__ int    g_outdeg[MAXN];
__device__ int    g_fill[MAXN];
__device__ int    g_rowptr[MAXN + 1];
__device__ int    g_blocksum[MAXSB];
__device__ int    g_blockoff[MAXSB];
__device__ float  g_wet[8];
__device__ Edge   g_edges[MAXE];
__device__ __align__(16) __half g_ha[(size_t)PADN * DDIM];
__device__ __align__(16) __half g_hb[(size_t)PADN * DDIM];
__device__ __align__(16) __half g_w1h[DDIM * DDIM];
__device__ __align__(16) __half g_w2h[DDIM * DDIM];

// ---------------------------------------------------------------------------
__global__ void zero_kernel(int N) {
    int i = blockIdx.x * blockDim.x + threadIdx.x;
    int stride = gridDim.x * blockDim.x;
    for (; i < N; i += stride) {
        g_indeg[i] = 0; g_outdeg[i] = 0; g_fill[i] = 0;
    }
}

// ---------------------------------------------------------------------------
// per-etype gate: wet[t] = 1 + sigmoid( gelu(emb[t]@We1+be1) @ We2 + be2 )
__global__ void gate_kernel(const float* __restrict__ emb,
                            const float* __restrict__ We1, const float* __restrict__ be1,
                            const float* __restrict__ We2, const float* __restrict__ be2) {
    __shared__ float eh[8][32];
    int t = threadIdx.x;          // 256 threads
    int et = t >> 5, j = t & 31;
    float dot = be1[j];
    #pragma unroll 8
    for (int i = 0; i < 128; i++) dot += emb[et * 128 + i] * We1[i * 32 + j];
    float g = 0.5f * dot * (1.0f + erff(dot * 0.70710678118654752f));
    eh[et][j] = g;
    __syncthreads();
    if (j == 0) {
        float d2 = be2[0];
        #pragma unroll
        for (int jj = 0; jj < 32; jj++) d2 += eh[et][jj] * We2[jj];
        float sg = 1.0f / (1.0f + expf(-d2));
        g_wet[et] = 1.0f + sg;
    }
}

// ---------------------------------------------------------------------------
__global__ void hist_kernel(const int* __restrict__ src, const int* __restrict__ dst, int E) {
    int i = blockIdx.x * blockDim.x + threadIdx.x;
    int stride = gridDim.x * blockDim.x;
    for (; i < E; i += stride) {
        atomicAdd(&g_outdeg[src[i]], 1);
        atomicAdd(&g_indeg[dst[i]], 1);
    }
}

// ---------------------------------------------------------------------------
// 3-phase exclusive scan of in-degrees -> rowptr
__global__ void scan_phase1(int N) {
    __shared__ int s[SCB];
    int b = blockIdx.x, t = threadIdx.x;
    int idx = b * SCB + t;
    int v = (idx < N) ? g_indeg[idx] : 0;
    s[t] = v; __syncthreads();
    #pragma unroll
    for (int off = SCB / 2; off > 0; off >>= 1) {
        if (t < off) s[t] += s[t + off];
        __syncthreads();
    }
    if (t == 0) g_blocksum[b] = s[0];
}

__global__ void scan_phase2(int NB, int N) {
    __shared__ int s[SCB];
    int t = threadIdx.x;
    int v = (t < NB) ? g_blocksum[t] : 0;
    s[t] = v; __syncthreads();
    #pragma unroll
    for (int off = 1; off < SCB; off <<= 1) {
        int x = (t >= off) ? s[t - off] : 0;
        __syncthreads();
        s[t] += x;
        __syncthreads();
    }
    g_blockoff[t] = s[t] - v;            // exclusive block offset
    if (t == NB - 1) g_rowptr[N] = s[t]; // total edge count
}

__global__ void scan_phase3(int N) {
    __shared__ int s[SCB];
    int b = blockIdx.x, t = threadIdx.x;
    int idx = b * SCB + t;
    int v = (idx < N) ? g_indeg[idx] : 0;
    s[t] = v; __syncthreads();
    #pragma unroll
    for (int off = 1; off < SCB; off <<= 1) {
        int x = (t >= off) ? s[t - off] : 0;
        __syncthreads();
        s[t] += x;
        __syncthreads();
    }
    if (idx < N) g_rowptr[idx] = g_blockoff[b] + s[t] - v;
}

// ---------------------------------------------------------------------------
__global__ void scatter_kernel(const int* __restrict__ src, const int* __restrict__ dst,
                               const int* __restrict__ ef, int E) {
    int i = blockIdx.x * blockDim.x + threadIdx.x;
    int stride = gridDim.x * blockDim.x;
    for (; i < E; i += stride) {
        int s = src[i], d = dst[i];
        float sn = rsqrtf((float)max(g_outdeg[s], 1));
        float dn = rsqrtf((float)max(g_indeg[d], 1));
        float c = g_wet[ef[i]] * sn * dn;
        int pos = g_rowptr[d] + atomicAdd(&g_fill[d], 1);
        Edge e; e.s = s; e.c = c;
        g_edges[pos] = e;
    }
}

// ---------------------------------------------------------------------------
__global__ void f2h_kernel(const float* __restrict__ in, __half* __restrict__ out, int n4) {
    int i = blockIdx.x * blockDim.x + threadIdx.x;
    if (i >= n4) return;
    float4 v = ((const float4*)in)[i];
    __half2 a = __floats2half2_rn(v.x, v.y);
    __half2 b = __floats2half2_rn(v.z, v.w);
    uint2 o; o.x = *(unsigned*)&a; o.y = *(unsigned*)&b;
    ((uint2*)out)[i] = o;
}

// ---------------------------------------------------------------------------
__global__ void w2h_kernel(const float* __restrict__ W1, const float* __restrict__ W2) {
    int i = blockIdx.x * blockDim.x + threadIdx.x;
    if (i < DDIM * DDIM) {
        g_w1h[i] = __float2half_rn(W1[i]);
        g_w2h[i] = __float2half_rn(W2[i]);
    }
}

// ---------------------------------------------------------------------------
// one hop: warp per dst row, lane = 4 consecutive features (8B half load)
__global__ void __launch_bounds__(256) hop_kernel(const __half* __restrict__ hin,
                                                  const float* __restrict__ feat,
                                                  __half* __restrict__ hout, int N) {
    int gw = (blockIdx.x * blockDim.x + threadIdx.x) >> 5;
    if (gw >= N) return;
    int lane = threadIdx.x & 31;

    int beg = g_rowptr[gw];
    int end = g_rowptr[gw + 1];

    float4 acc = make_float4(0.f, 0.f, 0.f, 0.f);

    int e = beg;
    // full chunks of 32 edges: fixed trip count -> unroll + pipeline
    for (; e + 32 <= end; e += 32) {
        Edge ed = g_edges[e + lane];
        int   es = ed.s;
        float ec = ed.c;
        #pragma unroll 8
        for (int j = 0; j < 32; ++j) {
            int   s = __shfl_sync(0xffffffffu, es, j);
            float c = __shfl_sync(0xffffffffu, ec, j);
            uint2 v = __ldg((const uint2*)(hin + (size_t)s * DDIM) + lane);
            float2 f0 = __half22float2(*(__half2*)&v.x);
            float2 f1 = __half22float2(*(__half2*)&v.y);
            acc.x = fmaf(c, f0.x, acc.x);
            acc.y = fmaf(c, f0.y, acc.y);
            acc.z = fmaf(c, f1.x, acc.z);
            acc.w = fmaf(c, f1.y, acc.w);
        }
    }
    int n = end - e;
    if (n > 0) {
        int   es = 0;
        float ec = 0.f;
        if (lane < n) {
            Edge ed = g_edges[e + lane];
            es = ed.s; ec = ed.c;
        }
        for (int j = 0; j < n; ++j) {
            int   s = __shfl_sync(0xffffffffu, es, j);
            float c = __shfl_sync(0xffffffffu, ec, j);
            uint2 v = __ldg((const uint2*)(hin + (size_t)s * DDIM) + lane);
            float2 f0 = __half22float2(*(__half2*)&v.x);
            float2 f1 = __half22float2(*(__half2*)&v.y);
            acc.x = fmaf(c, f0.x, acc.x);
            acc.y = fmaf(c, f0.y, acc.y);
            acc.z = fmaf(c, f1.x, acc.z);
            acc.w = fmaf(c, f1.y, acc.w);
        }
    }

    float4 f0 = ((const float4*)feat)[gw * 32 + lane];
    float ox = 0.9f * acc.x + 0.1f * f0.x;
    float oy = 0.9f * acc.y + 0.1f * f0.y;
    float oz = 0.9f * acc.z + 0.1f * f0.z;
    float ow = 0.9f * acc.w + 0.1f * f0.w;
    __half2 a = __floats2half2_rn(ox, oy);
    __half2 b = __floats2half2_rn(oz, ow);
    uint2 o; o.x = *(unsigned*)&a; o.y = *(unsigned*)&b;
    ((uint2*)hout)[gw * 32 + lane] = o;
}

// ---------------------------------------------------------------------------
// Tensor-core GEMM (M x 128) @ (128 x 128), fp16 in / fp32 accum.
// Block = 8 warps = 128 output rows x 128 cols. Warp = 32 rows x 64 cols
// (2x4 wmma 16x16x16 frags). W staged in smem; per-warp smem epilogue fuses
// bias + exact GELU; outputs half (intermediate) or float (final).
#define EPI_LD 72   // padded row stride (floats) for epilogue tile
template <bool GELU, bool OUTHALF>
__global__ void __launch_bounds__(256) hgemm_kernel(const __half* __restrict__ A,
                                                    const __half* __restrict__ W,
                                                    const float* __restrict__ bias,
                                                    __half* __restrict__ outh,
                                                    float* __restrict__ outf, int M) {
    extern __shared__ char smraw[];
    __half* Ws = (__half*)smraw;                   // 128*128 half = 32768 B
    float*  Es = (float*)(smraw + 32768);          // 8 * 32*EPI_LD floats = 73728 B

    int t = threadIdx.x, wid = t >> 5, lane = t & 31;

    // stage W
    const uint4* Wv = (const uint4*)W;
    uint4* Wsv = (uint4*)Ws;
    #pragma unroll
    for (int i = t; i < 2048; i += 256) Wsv[i] = Wv[i];
    __syncthreads();

    int wy = wid & 3, wx = wid >> 2;
    int row0 = blockIdx.x * 128 + wy * 32;
    int col0 = wx * 64;

    wmma::fragment<wmma::accumulator, 16, 16, 16, float> acc[2][4];
    #pragma unroll
    for (int i = 0; i < 2; i++)
        #pragma unroll
        for (int j = 0; j < 4; j++) wmma::fill_fragment(acc[i][j], 0.0f);

    #pragma unroll
    for (int kk = 0; kk < 8; kk++) {
        wmma::fragment<wmma::matrix_a, 16, 16, 16, __half, wmma::row_major> af[2];
        wmma::fragment<wmma::matrix_b, 16, 16, 16, __half, wmma::row_major> bf[4];
        #pragma unroll
        for (int i = 0; i < 2; i++)
            wmma::load_matrix_sync(af[i], A + (size_t)(row0 + i * 16) * DDIM + kk * 16, DDIM);
        #pragma unroll
        for (int j = 0; j < 4; j++)
            wmma::load_matrix_sync(bf[j], Ws + kk * 16 * DDIM + col0 + j * 16, DDIM);
        #pragma unroll
        for (int i = 0; i < 2; i++)
            #pragma unroll
            for (int j = 0; j < 4; j++)
                wmma::mma_sync(acc[i][j], af[i], bf[j], acc[i][j]);
    }

    // per-warp epilogue (no block sync needed; warp-exclusive smem region)
    float* es = Es + wid * (32 * EPI_LD);
    #pragma unroll
    for (int i = 0; i < 2; i++)
        #pragma unroll
        for (int j = 0; j < 4; j++)
            wmma::store_matrix_sync(es + i * 16 * EPI_LD + j * 16, acc[i][j],
                                    EPI_LD, wmma::mem_row_major);
    __syncwarp();

    int grow = row0 + lane;                 // each lane owns one row of the 32
    if (grow < M) {
        #pragma unroll
        for (int c4 = 0; c4 < 16; c4++) {
            float4 v = *(float4*)&es[lane * EPI_LD + c4 * 4];
            int col = col0 + c4 * 4;
            float4 b = *(const float4*)&bias[col];
            v.x += b.x; v.y += b.y; v.z += b.z; v.w += b.w;
            if (GELU) {
                v.x = 0.5f * v.x * (1.0f + erff(v.x * 0.70710678118654752f));
                v.y = 0.5f * v.y * (1.0f + erff(v.y * 0.70710678118654752f));
                v.z = 0.5f * v.z * (1.0f + erff(v.z * 0.70710678118654752f));
                v.w = 0.5f * v.w * (1.0f + erff(v.w * 0.70710678118654752f));
            }
            if (OUTHALF) {
                __half2 h0 = __floats2half2_rn(v.x, v.y);
                __half2 h1 = __floats2half2_rn(v.z, v.w);
                uint2 o; o.x = *(unsigned*)&h0; o.y = *(unsigned*)&h1;
                *(uint2*)&outh[(size_t)grow * DDIM + col] = o;
            } else {
                *(float4*)&outf[(size_t)grow * DDIM + col] = v;
            }
        }
    }
}

// ---------------------------------------------------------------------------
extern "C" void kernel_launch(void* const* d_in, const int* in_sizes, int n_in,
                              void* d_out, int out_size) {
    const float* feat = (const float*)d_in[0];
    const int*   ef   = (const int*)d_in[1];
    const int*   src  = (const int*)d_in[2];
    const int*   dst  = (const int*)d_in[3];
    const float* emb  = (const float*)d_in[4];
    const float* We1  = (const float*)d_in[5];
    const float* be1  = (const float*)d_in[6];
    const float* We2  = (const float*)d_in[7];
    const float* be2  = (const float*)d_in[8];
    const float* W1   = (const float*)d_in[9];
    const float* b1   = (const float*)d_in[10];
    const float* W2   = (const float*)d_in[11];
    const float* b2   = (const float*)d_in[12];
    float* out = (float*)d_out;

    int N = in_sizes[0] / DDIM;   // 50000
    int E = in_sizes[1];          // 1600000

    void *pa = nullptr, *pb = nullptr, *pw1 = nullptr, *pw2 = nullptr;
    cudaGetSymbolAddress(&pa, g_ha);
    cudaGetSymbolAddress(&pb, g_hb);
    cudaGetSymbolAddress(&pw1, g_w1h);
    cudaGetSymbolAddress(&pw2, g_w2h);
    __half* ha  = (__half*)pa;
    __half* hb  = (__half*)pb;
    __half* w1h = (__half*)pw1;
    __half* w2h = (__half*)pw2;

    const int GEMM_SMEM = 32768 + 8 * 32 * EPI_LD * 4;   // 106496
    cudaFuncSetAttribute(hgemm_kernel<true, true>,
                         cudaFuncAttributeMaxDynamicSharedMemorySize, GEMM_SMEM);
    cudaFuncSetAttribute(hgemm_kernel<false, false>,
                         cudaFuncAttributeMaxDynamicSharedMemorySize, GEMM_SMEM);

    // --- build phase ---
    zero_kernel<<<(N + 255) / 256, 256>>>(N);
    gate_kernel<<<1, 256>>>(emb, We1, be1, We2, be2);
    w2h_kernel<<<(DDIM * DDIM + 255) / 256, 256>>>(W1, W2);
    hist_kernel<<<2048, 256>>>(src, dst, E);
    int NB = (N + SCB - 1) / SCB;  // 196
    scan_phase1<<<NB, SCB>>>(N);
    scan_phase2<<<1, SCB>>>(NB, N);
    scan_phase3<<<NB, SCB>>>(N);
    scatter_kernel<<<2048, 256>>>(src, dst, ef, E);

    // feat -> half (hop 0 input)
    int n4 = N * DDIM / 4;
    f2h_kernel<<<(n4 + 255) / 256, 256>>>(feat, ha, n4);

    // --- K=10 propagation hops (half ping-pong; hop 9 lands in ha) ---
    int hop_blocks = (N * 32 + 255) / 256;
    for (int k = 0; k < 10; k++) {
        const __half* hin  = (k & 1) ? hb : ha;
        __half*       hout = (k & 1) ? ha : hb;
        hop_kernel<<<hop_blocks, 256>>>(hin, feat, hout, N);
    }

    // --- output MLP (tensor cores) ---
    int gblocks = PADN / 128;   // 392
    hgemm_kernel<true,  true ><<<gblocks, 256, GEMM_SMEM>>>(ha, w1h, b1, hb, nullptr, N);
    hgemm_kernel<false, false><<<gblocks, 256, GEMM_SMEM>>>(hb, w2h, b2, nullptr, out, N);
}

// round 4
// speedup vs baseline: 1.5414x; 1.0142x over previous
#include <cuda_runtime.h>
#include <cuda_fp16.h>
#include <mma.h>
#include <math.h>

using namespace nvcuda;

#define MAXN 50000
#define PADN 50176   // 392*128, covers GEMM row tiles
#define MAXE 1600000
#define DDIM 128
#define SCB 256
#define MAXSB 256

struct __align__(8) Edge { int s; float c; };

// ---- device scratch (no allocation allowed) ----
__device__ int    g_indeg[MAXN];
__device__ int    g_outdeg[MAXN];
__device__ int    g_rowptr[MAXN + 1];
__device__ int    g_blocksum[MAXSB];
__device__ int    g_blockoff[MAXSB];
__device__ float  g_wet[8];
__device__ float  g_sn[MAXN];     // src-side norm
__device__ float  g_dn9[MAXN];    // 0.9 * dst-side norm
__device__ int    g_rank[MAXE];   // per-edge slot within its dst row
__device__ Edge   g_edges[MAXE];
__device__ __align__(16) __half g_ha[(size_t)PADN * DDIM];
__device__ __align__(16) __half g_hb[(size_t)PADN * DDIM];
__device__ __align__(16) __half g_res[(size_t)PADN * DDIM];  // 0.1*feat, half
__device__ __align__(16) __half g_w1h[DDIM * DDIM];
__device__ __align__(16) __half g_w2h[DDIM * DDIM];

// ---------------------------------------------------------------------------
__global__ void zero_kernel(int N) {
    int i = blockIdx.x * blockDim.x + threadIdx.x;
    int stride = gridDim.x * blockDim.x;
    for (; i < N; i += stride) {
        g_indeg[i] = 0; g_outdeg[i] = 0;
    }
}

// ---------------------------------------------------------------------------
// per-etype gate: wet[t] = 1 + sigmoid( gelu(emb[t]@We1+be1) @ We2 + be2 )
__global__ void gate_kernel(const float* __restrict__ emb,
                            const float* __restrict__ We1, const float* __restrict__ be1,
                            const float* __restrict__ We2, const float* __restrict__ be2) {
    __shared__ float eh[8][32];
    int t = threadIdx.x;          // 256 threads
    int et = t >> 5, j = t & 31;
    float dot = be1[j];
    #pragma unroll 8
    for (int i = 0; i < 128; i++) dot += emb[et * 128 + i] * We1[i * 32 + j];
    float g = 0.5f * dot * (1.0f + erff(dot * 0.70710678118654752f));
    eh[et][j] = g;
    __syncthreads();
    if (j == 0) {
        float d2 = be2[0];
        #pragma unroll
        for (int jj = 0; jj < 32; jj++) d2 += eh[et][jj] * We2[jj];
        float sg = 1.0f / (1.0f + expf(-d2));
        g_wet[et] = 1.0f + sg;
    }
}

// ---------------------------------------------------------------------------
// degree histogram; indeg atomic return value = edge's rank within its dst row
__global__ void hist_kernel(const int* __restrict__ src, const int* __restrict__ dst, int E) {
    int i = blockIdx.x * blockDim.x + threadIdx.x;
    int stride = gridDim.x * blockDim.x;
    for (; i < E; i += stride) {
        atomicAdd(&g_outdeg[src[i]], 1);
        g_rank[i] = atomicAdd(&g_indeg[dst[i]], 1);
    }
}

// ---------------------------------------------------------------------------
// 3-phase exclusive scan of in-degrees -> rowptr
__global__ void scan_phase1(int N) {
    __shared__ int s[SCB];
    int b = blockIdx.x, t = threadIdx.x;
    int idx = b * SCB + t;
    int v = (idx < N) ? g_indeg[idx] : 0;
    s[t] = v; __syncthreads();
    #pragma unroll
    for (int off = SCB / 2; off > 0; off >>= 1) {
        if (t < off) s[t] += s[t + off];
        __syncthreads();
    }
    if (t == 0) g_blocksum[b] = s[0];
}

__global__ void scan_phase2(int NB, int N) {
    __shared__ int s[SCB];
    int t = threadIdx.x;
    int v = (t < NB) ? g_blocksum[t] : 0;
    s[t] = v; __syncthreads();
    #pragma unroll
    for (int off = 1; off < SCB; off <<= 1) {
        int x = (t >= off) ? s[t - off] : 0;
        __syncthreads();
        s[t] += x;
        __syncthreads();
    }
    g_blockoff[t] = s[t] - v;            // exclusive block offset
    if (t == NB - 1) g_rowptr[N] = s[t]; // total edge count
}

// phase3 also finalizes per-node norms (degrees are final here)
__global__ void scan_phase3(int N) {
    __shared__ int s[SCB];
    int b = blockIdx.x, t = threadIdx.x;
    int idx = b * SCB + t;
    int v = (idx < N) ? g_indeg[idx] : 0;
    s[t] = v; __syncthreads();
    #pragma unroll
    for (int off = 1; off < SCB; off <<= 1) {
        int x = (t >= off) ? s[t - off] : 0;
        __syncthreads();
        s[t] += x;
        __syncthreads();
    }
    if (idx < N) {
        g_rowptr[idx] = g_blockoff[b] + s[t] - v;
        g_sn[idx]  = rsqrtf((float)max(g_outdeg[idx], 1));
        g_dn9[idx] = 0.9f * rsqrtf((float)max(v, 1));
    }
}

// ---------------------------------------------------------------------------
// scatter edges into CSR slots; c folds gate * src_norm only (dst_norm at row level)
__global__ void scatter_kernel(const int* __restrict__ src, const int* __restrict__ dst,
                               const int* __restrict__ ef, int E) {
    int i = blockIdx.x * blockDim.x + threadIdx.x;
    int stride = gridDim.x * blockDim.x;
    for (; i < E; i += stride) {
        int s = src[i], d = dst[i];
        float c = g_wet[ef[i]] * g_sn[s];
        int pos = g_rowptr[d] + g_rank[i];
        Edge e; e.s = s; e.c = c;
        g_edges[pos] = e;
    }
}

// ---------------------------------------------------------------------------
// fp32 feat -> half hop buffer + half prescaled residual (0.1*feat)
__global__ void f2h_kernel(const float* __restrict__ in, __half* __restrict__ h,
                           __half* __restrict__ res, int n4) {
    int i = blockIdx.x * blockDim.x + threadIdx.x;
    if (i >= n4) return;
    float4 v = ((const float4*)in)[i];
    __half2 a = __floats2half2_rn(v.x, v.y);
    __half2 b = __floats2half2_rn(v.z, v.w);
    uint2 o; o.x = *(unsigned*)&a; o.y = *(unsigned*)&b;
    ((uint2*)h)[i] = o;
    __half2 ra = __floats2half2_rn(0.1f * v.x, 0.1f * v.y);
    __half2 rb = __floats2half2_rn(0.1f * v.z, 0.1f * v.w);
    uint2 r; r.x = *(unsigned*)&ra; r.y = *(unsigned*)&rb;
    ((uint2*)res)[i] = r;
}

// ---------------------------------------------------------------------------
__global__ void w2h_kernel(const float* __restrict__ W1, const float* __restrict__ W2) {
    int i = blockIdx.x * blockDim.x + threadIdx.x;
    if (i < DDIM * DDIM) {
        g_w1h[i] = __float2half_rn(W1[i]);
        g_w2h[i] = __float2half_rn(W2[i]);
    }
}

// ---------------------------------------------------------------------------
// one hop: warp per dst row, lane = 4 consecutive features (8B half load)
// out = (0.9*dn[row]) * sum_e c_e * h[src_e] + res[row]
__global__ void __launch_bounds__(256) hop_kernel(const __half* __restrict__ hin,
                                                  __half* __restrict__ hout, int N) {
    int gw = (blockIdx.x * blockDim.x + threadIdx.x) >> 5;
    if (gw >= N) return;
    int lane = threadIdx.x & 31;

    int beg = g_rowptr[gw];
    int end = g_rowptr[gw + 1];

    float4 acc = make_float4(0.f, 0.f, 0.f, 0.f);

    int e = beg;
    for (; e + 32 <= end; e += 32) {
        Edge ed = g_edges[e + lane];
        int   es = ed.s;
        float ec = ed.c;
        #pragma unroll 8
        for (int j = 0; j < 32; ++j) {
            int   s = __shfl_sync(0xffffffffu, es, j);
            float c = __shfl_sync(0xffffffffu, ec, j);
            uint2 v = __ldg((const uint2*)(hin + (size_t)s * DDIM) + lane);
            float2 f0 = __half22float2(*(__half2*)&v.x);
            float2 f1 = __half22float2(*(__half2*)&v.y);
            acc.x = fmaf(c, f0.x, acc.x);
            acc.y = fmaf(c, f0.y, acc.y);
            acc.z = fmaf(c, f1.x, acc.z);
            acc.w = fmaf(c, f1.y, acc.w);
        }
    }
    int n = end - e;
    if (n > 0) {
        int   es = 0;
        float ec = 0.f;
        if (lane < n) {
            Edge ed = g_edges[e + lane];
            es = ed.s; ec = ed.c;
        }
        for (int j = 0; j < n; ++j) {
            int   s = __shfl_sync(0xffffffffu, es, j);
            float c = __shfl_sync(0xffffffffu, ec, j);
            uint2 v = __ldg((const uint2*)(hin + (size_t)s * DDIM) + lane);
            float2 f0 = __half22float2(*(__half2*)&v.x);
            float2 f1 = __half22float2(*(__half2*)&v.y);
            acc.x = fmaf(c, f0.x, acc.x);
            acc.y = fmaf(c, f0.y, acc.y);
            acc.z = fmaf(c, f1.x, acc.z);
            acc.w = fmaf(c, f1.y, acc.w);
        }
    }

    float dn9 = g_dn9[gw];
    uint2 rv = ((const uint2*)g_res)[gw * 32 + lane];
    float2 r0 = __half22float2(*(__half2*)&rv.x);
    float2 r1 = __half22float2(*(__half2*)&rv.y);
    float ox = fmaf(dn9, acc.x, r0.x);
    float oy = fmaf(dn9, acc.y, r0.y);
    float oz = fmaf(dn9, acc.z, r1.x);
    float ow = fmaf(dn9, acc.w, r1.y);
    __half2 a = __floats2half2_rn(ox, oy);
    __half2 b = __floats2half2_rn(oz, ow);
    uint2 o; o.x = *(unsigned*)&a; o.y = *(unsigned*)&b;
    ((uint2*)hout)[gw * 32 + lane] = o;
}

// ---------------------------------------------------------------------------
// Fused output MLP: out = gelu(A@W1+b1) @ W2 + b2, tensor cores, fp32 accum.
// Block = 8 warps = 128 rows. Intermediate held as half tile in smem.
#define EPI_LD 72   // padded row stride (floats) for per-warp epilogue scratch
__global__ void __launch_bounds__(256) mlp_kernel(const __half* __restrict__ A,
                                                  const float* __restrict__ b1,
                                                  const float* __restrict__ b2,
                                                  float* __restrict__ Out, int M) {
    extern __shared__ char smraw[];
    __half* W1s = (__half*)smraw;                    //     0..32768
    __half* W2s = (__half*)(smraw + 32768);          // 32768..65536
    __half* A2  = (__half*)(smraw + 65536);          // 65536..98304 (128x128 half)
    float*  Es  = (float*)(smraw + 98304);           // 8 * 32*EPI_LD floats

    int t = threadIdx.x, wid = t >> 5, lane = t & 31;

    {   // stage both weight matrices
        const uint4* w1 = (const uint4*)g_w1h;
        const uint4* w2 = (const uint4*)g_w2h;
        uint4* d1 = (uint4*)W1s;
        uint4* d2 = (uint4*)W2s;
        #pragma unroll
        for (int i = t; i < 2048; i += 256) { d1[i] = w1[i]; d2[i] = w2[i]; }
    }
    __syncthreads();

    int wy = wid & 3, wx = wid >> 2;
    int row0 = blockIdx.x * 128 + wy * 32;   // global row base for this warp
    int lrow0 = wy * 32;                     // local row base within A2
    int col0 = wx * 64;

    float* es = Es + wid * (32 * EPI_LD);

    // ---- pass 1: A @ W1 ----
    wmma::fragment<wmma::accumulator, 16, 16, 16, float> acc[2][4];
    #pragma unroll
    for (int i = 0; i < 2; i++)
        #pragma unroll
        for (int j = 0; j < 4; j++) wmma::fill_fragment(acc[i][j], 0.0f);

    #pragma unroll
    for (int kk = 0; kk < 8; kk++) {
        wmma::fragment<wmma::matrix_a, 16, 16, 16, __half, wmma::row_major> af[2];
        wmma::fragment<wmma::matrix_b, 16, 16, 16, __half, wmma::row_major> bf[4];
        #pragma unroll
        for (int i = 0; i < 2; i++)
            wmma::load_matrix_sync(af[i], A + (size_t)(row0 + i * 16) * DDIM + kk * 16, DDIM);
        #pragma unroll
        for (int j = 0; j < 4; j++)
            wmma::load_matrix_sync(bf[j], W1s + kk * 16 * DDIM + col0 + j * 16, DDIM);
        #pragma unroll
        for (int i = 0; i < 2; i++)
            #pragma unroll
            for (int j = 0; j < 4; j++)
                wmma::mma_sync(acc[i][j], af[i], bf[j], acc[i][j]);
    }

    // epilogue 1: bias + exact GELU -> half tile A2
    #pragma unroll
    for (int i = 0; i < 2; i++)
        #pragma unroll
        for (int j = 0; j < 4; j++)
            wmma::store_matrix_sync(es + i * 16 * EPI_LD + j * 16, acc[i][j],
                                    EPI_LD, wmma::mem_row_major);
    __syncwarp();
    {
        int lr = lrow0 + lane;   // local row this lane owns
        #pragma unroll
        for (int c4 = 0; c4 < 16; c4++) {
            float4 v = *(float4*)&es[lane * EPI_LD + c4 * 4];
            int col = col0 + c4 * 4;
            float4 b = *(const float4*)&b1[col];
            v.x += b.x; v.y += b.y; v.z += b.z; v.w += b.w;
            v.x = 0.5f * v.x * (1.0f + erff(v.x * 0.70710678118654752f));
            v.y = 0.5f * v.y * (1.0f + erff(v.y * 0.70710678118654752f));
            v.z = 0.5f * v.z * (1.0f + erff(v.z * 0.70710678118654752f));
            v.w = 0.5f * v.w * (1.0f + erff(v.w * 0.70710678118654752f));
            __half2 h0 = __floats2half2_rn(v.x, v.y);
            __half2 h1 = __floats2half2_rn(v.z, v.w);
            uint2 o; o.x = *(unsigned*)&h0; o.y = *(unsigned*)&h1;
            *(uint2*)&A2[(size_t)lr * DDIM + col] = o;
        }
    }
    __syncthreads();   // full A2 needed by all warps

    // ---- pass 2: gelu-tile @ W2 ----
    #pragma unroll
    for (int i = 0; i < 2; i++)
        #pragma unroll
        for (int j = 0; j < 4; j++) wmma::fill_fragment(acc[i][j], 0.0f);

    #pragma unroll
    for (int kk = 0; kk < 8; kk++) {
        wmma::fragment<wmma::matrix_a, 16, 16, 16, __half, wmma::row_major> af[2];
        wmma::fragment<wmma::matrix_b, 16, 16, 16, __half, wmma::row_major> bf[4];
        #pragma unroll
        for (int i = 0; i < 2; i++)
            wmma::load_matrix_sync(af[i], A2 + (size_t)(lrow0 + i * 16) * DDIM + kk * 16, DDIM);
        #pragma unroll
        for (int j = 0; j < 4; j++)
            wmma::load_matrix_sync(bf[j], W2s + kk * 16 * DDIM + col0 + j * 16, DDIM);
        #pragma unroll
        for (int i = 0; i < 2; i++)
            #pragma unroll
            for (int j = 0; j < 4; j++)
                wmma::mma_sync(acc[i][j], af[i], bf[j], acc[i][j]);
    }

    // epilogue 2: bias -> fp32 out
    #pragma unroll
    for (int i = 0; i < 2; i++)
        #pragma unroll
        for (int j = 0; j < 4; j++)
            wmma::store_matrix_sync(es + i * 16 * EPI_LD + j * 16, acc[i][j],
                                    EPI_LD, wmma::mem_row_major);
    __syncwarp();
    {
        int grow = row0 + lane;
        if (grow < M) {
            #pragma unroll
            for (int c4 = 0; c4 < 16; c4++) {
                float4 v = *(float4*)&es[lane * EPI_LD + c4 * 4];
                int col = col0 + c4 * 4;
                float4 b = *(const float4*)&b2[col];
                v.x += b.x; v.y += b.y; v.z += b.z; v.w += b.w;
                *(float4*)&Out[(size_t)grow * DDIM + col] = v;
            }
        }
    }
}

// ---------------------------------------------------------------------------
extern "C" void kernel_launch(void* const* d_in, const int* in_sizes, int n_in,
                              void* d_out, int out_size) {
    const float* feat = (const float*)d_in[0];
    const int*   ef   = (const int*)d_in[1];
    const int*   src  = (const int*)d_in[2];
    const int*   dst  = (const int*)d_in[3];
    const float* emb  = (const float*)d_in[4];
    const float* We1  = (const float*)d_in[5];
    const float* be1  = (const float*)d_in[6];
    const float* We2  = (const float*)d_in[7];
    const float* be2  = (const float*)d_in[8];
    const float* W1   = (const float*)d_in[9];
    const float* b1   = (const float*)d_in[10];
    const float* W2   = (const float*)d_in[11];
    const float* b2   = (const float*)d_in[12];
    float* out = (float*)d_out;

    int N = in_sizes[0] / DDIM;   // 50000
    int E = in_sizes[1];          // 1600000

    void *pa = nullptr, *pb = nullptr, *pr = nullptr;
    cudaGetSymbolAddress(&pa, g_ha);
    cudaGetSymbolAddress(&pb, g_hb);
    cudaGetSymbolAddress(&pr, g_res);
    __half* ha  = (__half*)pa;
    __half* hb  = (__half*)pb;
    __half* res = (__half*)pr;

    const int MLP_SMEM = 98304 + 8 * 32 * EPI_LD * 4;   // 98304 + 73728 = 172032
    cudaFuncSetAttribute(mlp_kernel, cudaFuncAttributeMaxDynamicSharedMemorySize, MLP_SMEM);

    // --- build phase ---
    zero_kernel<<<(N + 255) / 256, 256>>>(N);
    gate_kernel<<<1, 256>>>(emb, We1, be1, We2, be2);
    w2h_kernel<<<(DDIM * DDIM + 255) / 256, 256>>>(W1, W2);
    hist_kernel<<<2048, 256>>>(src, dst, E);
    int NB = (N + SCB - 1) / SCB;  // 196
    scan_phase1<<<NB, SCB>>>(N);
    scan_phase2<<<1, SCB>>>(NB, N);
    scan_phase3<<<NB, SCB>>>(N);
    scatter_kernel<<<2048, 256>>>(src, dst, ef, E);

    // feat -> half hop buffer + half prescaled residual
    int n4 = N * DDIM / 4;
    f2h_kernel<<<(n4 + 255) / 256, 256>>>(feat, ha, res, n4);

    // --- K=10 propagation hops (half ping-pong; hop 9 lands in ha) ---
    int hop_blocks = (N * 32 + 255) / 256;
    for (int k = 0; k < 10; k++) {
        const __half* hin  = (k & 1) ? hb : ha;
        __half*       hout = (k & 1) ? ha : hb;
        hop_kernel<<<hop_blocks, 256>>>(hin, hout, N);
    }

    // --- fused output MLP (tensor cores) ---
    int gblocks = PADN / 128;   // 392
    mlp_kernel<<<gblocks, 256, MLP_SMEM>>>(ha, b1, b2, out, N);
}